// round 11
// baseline (speedup 1.0000x reference)
#include <cuda_runtime.h>
#include <cuda_bf16.h>
#include <cstdint>

#define NT     128
#define TSTEPS 8191
#define NCH    148
#define NQ     37          // NCH / 4

// ---------------- global scratch (static) ----------------
__device__ __align__(16) float    g_E[NT * NT];       // exp(T), fp32
__device__ float                  g_csum[NT];         // col sums of exp(T)
__device__ __align__(16) float    g_d[TSTEPS * NT];   // exp(emit)*2^-k_t, scaled
__device__ int                    g_k[TSTEPS];        // per-step pow2 scales
__device__ __align__(16) uint32_t g_Bfrag[8192];      // E as bf16x2 mma B-fragments
__device__ __align__(16) float    g_P[NCH * NT * NT]; // chunk products
__device__ __align__(16) float    g_Q[NQ * NT * NT];  // folded products (4 chunks each)
__device__ int                    g_kf[NQ];           // fold pow2 scales

// ---------------- helpers ----------------
__device__ __forceinline__ uint32_t pack_bf16x2(float lo, float hi) {
    uint32_t r;
    asm("cvt.rn.bf16x2.f32 %0, %1, %2;" : "=r"(r) : "f"(hi), "f"(lo));
    return r;
}
__device__ __forceinline__ void mma16(float& c0, float& c1, float& c2, float& c3,
                                      uint32_t a0, uint32_t a1, uint32_t a2, uint32_t a3,
                                      uint32_t b0, uint32_t b1) {
    asm volatile("mma.sync.aligned.m16n8k16.row.col.f32.bf16.bf16.f32 "
                 "{%0,%1,%2,%3},{%4,%5,%6,%7},{%8,%9},{%0,%1,%2,%3};"
                 : "+f"(c0), "+f"(c1), "+f"(c2), "+f"(c3)
                 : "r"(a0), "r"(a1), "r"(a2), "r"(a3), "r"(b0), "r"(b1));
}
__device__ __forceinline__ void cp16(void* s, const void* g) {
    uint32_t sa = (uint32_t)__cvta_generic_to_shared(s);
    asm volatile("cp.async.ca.shared.global [%0], [%1], 16;" :: "r"(sa), "l"(g) : "memory");
}
#define CP_COMMIT() asm volatile("cp.async.commit_group;" ::: "memory")
#define CP_WAIT(n)  asm volatile("cp.async.wait_group %0;" :: "n"(n) : "memory")

// ---------------- prep 1: E = exp(T), col sums, B fragments ----------------
__global__ void prep_E(const float* __restrict__ trans) {
    const int j = threadIdx.x;
    float cs = 0.0f;
    for (int k = 0; k < NT; k++) {
        float e = __expf(trans[k * NT + j]);
        g_E[k * NT + j] = e;
        cs += e;
    }
    g_csum[j] = cs;

    const int l = j & 31, m = l & 3, n8 = l >> 2;
    const int ktbase = (j >> 5) * 2;
    for (int kt2 = ktbase; kt2 < ktbase + 2; kt2++)
        for (int nt = 0; nt < 16; nt++) {
            int n = 8 * nt + n8, k0 = 16 * kt2 + 2 * m;
            uint32_t b0 = pack_bf16x2(__expf(trans[(k0)     * NT + n]),
                                      __expf(trans[(k0 + 1) * NT + n]));
            uint32_t b1 = pack_bf16x2(__expf(trans[(k0 + 8) * NT + n]),
                                      __expf(trans[(k0 + 9) * NT + n]));
            int idx = ((kt2 * 16 + nt) * 32 + l) * 2;
            g_Bfrag[idx] = b0;
            g_Bfrag[idx + 1] = b1;
        }
}

// ---------------- prep 2: gather emissions, exp, per-step pow2 scale ----
__global__ void prep_D(const int* __restrict__ x, const float* __restrict__ emit) {
    __shared__ float sw[NT];
    const int t = blockIdx.x, j = threadIdx.x;
    float w = __expf(emit[(long long)x[t + 1] * NT + j]);
    sw[j] = w * g_csum[j];
    __syncthreads();
    for (int off = 64; off; off >>= 1) {
        if (j < off) sw[j] += sw[j + off];
        __syncthreads();
    }
    int kt = (((__float_as_int(sw[0]) >> 23) & 255) - 127) - 7;  // mean rowsum in [1,2)
    g_d[t * NT + j] = ldexpf(w, -kt);
    if (j == 0) g_k[t] = kt;
}

// ---------------- chunk kernel (unchanged, passing) ----------------
__global__ void __launch_bounds__(128, 1) chunk_kernel() {
    __shared__ __align__(16) uint32_t sB[8192];
    __shared__ __align__(16) float    sd[4][2][NT];

    const int tid = threadIdx.x, w = tid >> 5, l = tid & 31, m = l & 3;
    const int c  = blockIdx.x;
    const int t0 = (c * TSTEPS) / NCH;
    const int S  = ((c + 1) * TSTEPS) / NCH - t0;

    {
        const uint4* src = (const uint4*)g_Bfrag;
        uint4* dst = (uint4*)sB;
        for (int i = tid; i < 2048; i += 128) dst[i] = src[i];
    }
    cp16(&sd[w][0][l * 4], &g_d[(size_t)t0 * NT + l * 4]);
    CP_COMMIT();
    CP_WAIT(0);
    __syncwarp();
    __syncthreads();

    float C[2][16][4];
    const int r0 = 32 * w + (l >> 2);
#pragma unroll
    for (int rt = 0; rt < 2; rt++)
#pragma unroll
        for (int nt = 0; nt < 16; nt++) {
            int rr = r0 + 16 * rt, cc = 8 * nt + 2 * m;
            float2 v0 = *(const float2*)&g_E[rr * NT + cc];
            float2 v1 = *(const float2*)&g_E[(rr + 8) * NT + cc];
            C[rt][nt][0] = v0.x; C[rt][nt][1] = v0.y;
            C[rt][nt][2] = v1.x; C[rt][nt][3] = v1.y;
        }

    uint32_t A[2][8][4];
    for (int s = 0; s < S - 1; s++) {
        const int buf = s & 1;
        cp16(&sd[w][buf ^ 1][l * 4], &g_d[(size_t)(t0 + s + 1) * NT + l * 4]);
        CP_COMMIT();
        CP_WAIT(1);
        __syncwarp();

#pragma unroll
        for (int rt = 0; rt < 2; rt++)
#pragma unroll
            for (int kt2 = 0; kt2 < 8; kt2++) {
                float2 dA = *(const float2*)&sd[w][buf][16 * kt2 + 2 * m];
                float2 dB = *(const float2*)&sd[w][buf][16 * kt2 + 2 * m + 8];
                A[rt][kt2][0] = pack_bf16x2(C[rt][2 * kt2][0] * dA.x,     C[rt][2 * kt2][1] * dA.y);
                A[rt][kt2][1] = pack_bf16x2(C[rt][2 * kt2][2] * dA.x,     C[rt][2 * kt2][3] * dA.y);
                A[rt][kt2][2] = pack_bf16x2(C[rt][2 * kt2 + 1][0] * dB.x, C[rt][2 * kt2 + 1][1] * dB.y);
                A[rt][kt2][3] = pack_bf16x2(C[rt][2 * kt2 + 1][2] * dB.x, C[rt][2 * kt2 + 1][3] * dB.y);
            }
#pragma unroll
        for (int rt = 0; rt < 2; rt++)
#pragma unroll
            for (int nt = 0; nt < 16; nt++) {
                C[rt][nt][0] = 0.f; C[rt][nt][1] = 0.f;
                C[rt][nt][2] = 0.f; C[rt][nt][3] = 0.f;
            }
#pragma unroll
        for (int nt = 0; nt < 16; nt++)
#pragma unroll
            for (int kt2 = 0; kt2 < 8; kt2++) {
                uint2 b = *(const uint2*)&sB[((kt2 * 16 + nt) * 32 + l) * 2];
                mma16(C[0][nt][0], C[0][nt][1], C[0][nt][2], C[0][nt][3],
                      A[0][kt2][0], A[0][kt2][1], A[0][kt2][2], A[0][kt2][3], b.x, b.y);
                mma16(C[1][nt][0], C[1][nt][1], C[1][nt][2], C[1][nt][3],
                      A[1][kt2][0], A[1][kt2][1], A[1][kt2][2], A[1][kt2][3], b.x, b.y);
            }
    }

    CP_WAIT(0);
    __syncwarp();
    const int lastbuf = (S - 1) & 1;
    float* Pout = g_P + (size_t)c * NT * NT;
#pragma unroll
    for (int rt = 0; rt < 2; rt++)
#pragma unroll
        for (int nt = 0; nt < 16; nt++) {
            int rr = r0 + 16 * rt, cc = 8 * nt + 2 * m;
            float2 dv = *(const float2*)&sd[w][lastbuf][cc];
            float2 o0 = make_float2(C[rt][nt][0] * dv.x, C[rt][nt][1] * dv.y);
            float2 o1 = make_float2(C[rt][nt][2] * dv.x, C[rt][nt][3] * dv.y);
            *(float2*)&Pout[(size_t)rr * NT + cc]       = o0;
            *(float2*)&Pout[(size_t)(rr + 8) * NT + cc] = o1;
        }
}

// ---------------- fold4: Q_c = P_{4c} x P_{4c+1} x P_{4c+2} x P_{4c+3} ----------------
// 37 CTAs x 128 threads. Same fragment machinery as chunk; B-side renormed to <=1
// by its max exponent (recorded in g_kf). Staging buffer padded to 132 floats/row
// so fragment-build LDS reads are bank-conflict-free (bank = 8m + n8 + const).
#define RAWPITCH 132
__global__ void __launch_bounds__(128, 1) fold4_kernel() {
    extern __shared__ __align__(16) char fsm[];
    float*    sraw = (float*)fsm;                          // 128 x 132 floats
    uint32_t* sB   = (uint32_t*)(fsm + NT * RAWPITCH * 4); // 8192 words
    __shared__ float smax[NT];

    const int tid = threadIdx.x, w = tid >> 5, l = tid & 31, m = l & 3, n8 = l >> 2;
    const int c = blockIdx.x;
    const float* Pin0 = g_P + (size_t)(4 * c) * NT * NT;

    // C init = P_{4c} (fp32, raw) in C-fragment layout
    float C[2][16][4];
    const int r0 = 32 * w + (l >> 2);
#pragma unroll
    for (int rt = 0; rt < 2; rt++)
#pragma unroll
        for (int nt = 0; nt < 16; nt++) {
            int rr = r0 + 16 * rt, cc = 8 * nt + 2 * m;
            float2 v0 = *(const float2*)&Pin0[rr * NT + cc];
            float2 v1 = *(const float2*)&Pin0[(rr + 8) * NT + cc];
            C[rt][nt][0] = v0.x; C[rt][nt][1] = v0.y;
            C[rt][nt][2] = v1.x; C[rt][nt][3] = v1.y;
        }

    int ef = 0;
    uint32_t A[2][8][4];
    for (int s = 1; s < 4; s++) {
        // stage P_{4c+s} into padded SMEM (coalesced cp.async)
        const float* Pin = g_P + (size_t)(4 * c + s) * NT * NT;
        for (int u = tid; u < 4096; u += 128) {
            int row = u >> 5, qq = u & 31;
            cp16(&sraw[row * RAWPITCH + qq * 4], Pin + row * NT + qq * 4);
        }
        CP_COMMIT();
        CP_WAIT(0);
        __syncthreads();

        // max reduce -> power-of-2 scale so scaled B <= 1
        float mx = 0.0f;
        for (int u = tid; u < NT * NT; u += 128)
            mx = fmaxf(mx, sraw[(u >> 7) * RAWPITCH + (u & 127)]);
        smax[tid] = mx;
        __syncthreads();
        for (int off = 64; off; off >>= 1) {
            if (tid < off) smax[tid] = fmaxf(smax[tid], smax[tid + off]);
            __syncthreads();
        }
        int e = (((__float_as_int(smax[0]) >> 23) & 255) - 127) + 1;
        float sc = __int_as_float((uint32_t)(127 - e) << 23);   // exact 2^-e
        ef += e;

        // build bf16 B-fragments (conflict-free thanks to RAWPITCH=132)
#pragma unroll
        for (int kt2 = 2 * w; kt2 < 2 * w + 2; kt2++)
#pragma unroll
            for (int nt = 0; nt < 16; nt++) {
                int k0 = 16 * kt2 + 2 * m, n = 8 * nt + n8;
                float b00 = sraw[(k0)     * RAWPITCH + n] * sc;
                float b01 = sraw[(k0 + 1) * RAWPITCH + n] * sc;
                float b10 = sraw[(k0 + 8) * RAWPITCH + n] * sc;
                float b11 = sraw[(k0 + 9) * RAWPITCH + n] * sc;
                int idx = ((kt2 * 16 + nt) * 32 + l) * 2;
                sB[idx]     = pack_bf16x2(b00, b01);
                sB[idx + 1] = pack_bf16x2(b10, b11);
            }
        __syncthreads();

        // A = bf16(C), no diag
#pragma unroll
        for (int rt = 0; rt < 2; rt++)
#pragma unroll
            for (int kt2 = 0; kt2 < 8; kt2++) {
                A[rt][kt2][0] = pack_bf16x2(C[rt][2 * kt2][0],     C[rt][2 * kt2][1]);
                A[rt][kt2][1] = pack_bf16x2(C[rt][2 * kt2][2],     C[rt][2 * kt2][3]);
                A[rt][kt2][2] = pack_bf16x2(C[rt][2 * kt2 + 1][0], C[rt][2 * kt2 + 1][1]);
                A[rt][kt2][3] = pack_bf16x2(C[rt][2 * kt2 + 1][2], C[rt][2 * kt2 + 1][3]);
            }
#pragma unroll
        for (int rt = 0; rt < 2; rt++)
#pragma unroll
            for (int nt = 0; nt < 16; nt++) {
                C[rt][nt][0] = 0.f; C[rt][nt][1] = 0.f;
                C[rt][nt][2] = 0.f; C[rt][nt][3] = 0.f;
            }
#pragma unroll
        for (int nt = 0; nt < 16; nt++)
#pragma unroll
            for (int kt2 = 0; kt2 < 8; kt2++) {
                uint2 b = *(const uint2*)&sB[((kt2 * 16 + nt) * 32 + l) * 2];
                mma16(C[0][nt][0], C[0][nt][1], C[0][nt][2], C[0][nt][3],
                      A[0][kt2][0], A[0][kt2][1], A[0][kt2][2], A[0][kt2][3], b.x, b.y);
                mma16(C[1][nt][0], C[1][nt][1], C[1][nt][2], C[1][nt][3],
                      A[1][kt2][0], A[1][kt2][1], A[1][kt2][2], A[1][kt2][3], b.x, b.y);
            }
        __syncthreads();   // mma done before sraw/sB overwritten next s
    }

    float* Qout = g_Q + (size_t)c * NT * NT;
#pragma unroll
    for (int rt = 0; rt < 2; rt++)
#pragma unroll
        for (int nt = 0; nt < 16; nt++) {
            int rr = r0 + 16 * rt, cc = 8 * nt + 2 * m;
            *(float2*)&Qout[(size_t)rr * NT + cc]       = make_float2(C[rt][nt][0], C[rt][nt][1]);
            *(float2*)&Qout[(size_t)(rr + 8) * NT + cc] = make_float2(C[rt][nt][2], C[rt][nt][3]);
        }
    if (tid == 0) g_kf[c] = ef;
}

// ---------------- combine: chain of 37 matvecs, SMEM double-buffered ----------------
__global__ void __launch_bounds__(512, 1)
combine_kernel(const float* __restrict__ trans, float* __restrict__ out) {
    extern __shared__ __align__(16) float sQ[];   // 2 x 16384 floats
    __shared__ float w[NT];
    __shared__ float part[4][NT];
    __shared__ unsigned long long ks;
    const int tid = threadIdx.x, q = tid >> 7, j = tid & 127;

    long long kl = 0;
    for (int t = tid; t < TSTEPS; t += 512) kl += g_k[t];
    for (int t = tid; t < NQ; t += 512) kl += g_kf[t];
    if (tid == 0) ks = 0ull;
    if (q == 0) w[j] = (j == 0) ? 1.0f : 0.0f;
    __syncthreads();
    atomicAdd(&ks, (unsigned long long)kl);

#define PREF(buf, cc) do {                                                         \
        const float* _src = g_Q + (size_t)(cc) * NT * NT;                          \
        for (int v = 0; v < 8; v++) {                                              \
            int i = tid + 512 * v;                                                 \
            cp16(&sQ[(buf) * 16384 + i * 4], _src + i * 4);                        \
        }                                                                          \
        CP_COMMIT();                                                               \
    } while (0)

    PREF(0, 0);

    long long Kacc = 0;
    for (int cc = 0; cc < NQ; cc++) {
        const int buf = cc & 1;
        if (cc < NQ - 1) { PREF(buf ^ 1, cc + 1); CP_WAIT(1); }
        else             { CP_WAIT(0); }
        __syncthreads();                       // all threads' tiles visible

        const float* P = &sQ[buf * 16384];
        float acc = 0.0f;
        const int k0 = 32 * q;
#pragma unroll
        for (int k = k0; k < k0 + 32; k++) acc = fmaf(w[k], P[k * NT + j], acc);
        part[q][j] = acc;
        __syncthreads();

        float red  = part[0][j] + part[1][j] + part[2][j] + part[3][j];
        float red0 = part[0][0] + part[1][0] + part[2][0] + part[3][0];
        int k2 = ((__float_as_int(red0) >> 23) & 255) - 127;
        Kacc += k2;
        if (q == 0) w[j] = ldexpf(red, -k2);
        __syncthreads();
    }

    if (tid == 0) {
        float sum = 0.0f;
        for (int i = 0; i < NT; i++) sum += w[i] * __expf(trans[i * NT + 1]);  // END=1
        double z = (double)((long long)ks + Kacc) * 0.6931471805599453 +
                   log((double)sum);
        out[0] = (float)z;
    }
}

// ---------------- launch ----------------
extern "C" void kernel_launch(void* const* d_in, const int* in_sizes, int n_in,
                              void* d_out, int out_size) {
    const int* x = nullptr;
    const float* emit = nullptr;
    const float* trans = nullptr;
    for (int i = 0; i < n_in; i++) {
        if (in_sizes[i] == 8192)         x     = (const int*)d_in[i];
        else if (in_sizes[i] == NT * NT) trans = (const float*)d_in[i];
        else                             emit  = (const float*)d_in[i];
    }
    float* out = (float*)d_out;

    const int FOLD_SMEM = NT * RAWPITCH * 4 + 8192 * 4;   // 67584 + 32768 = 100352
    const int COMB_SMEM = 2 * NT * NT * 4;                // 131072
    cudaFuncSetAttribute(fold4_kernel,  cudaFuncAttributeMaxDynamicSharedMemorySize, FOLD_SMEM);
    cudaFuncSetAttribute(combine_kernel, cudaFuncAttributeMaxDynamicSharedMemorySize, COMB_SMEM);

    prep_E<<<1, NT>>>(trans);
    prep_D<<<TSTEPS, NT>>>(x, emit);
    chunk_kernel<<<NCH, 128>>>();
    fold4_kernel<<<NQ, 128, FOLD_SMEM>>>();
    combine_kernel<<<1, 512, COMB_SMEM>>>(trans, out);
}

// round 12
// speedup vs baseline: 1.0059x; 1.0059x over previous
#include <cuda_runtime.h>
#include <cuda_bf16.h>
#include <cstdint>

#define NT     128
#define TSTEPS 8191
#define NCH    148
#define NQ     37          // NCH / 4

// ---------------- global scratch (static) ----------------
__device__ __align__(16) float    g_E[NT * NT];       // exp(T), fp32
__device__ float                  g_csum[NT];         // col sums of exp(T)
__device__ __align__(16) float    g_d[TSTEPS * NT];   // exp(emit)*2^-k_t, scaled
__device__ int                    g_k[TSTEPS];        // per-step pow2 scales
__device__ __align__(16) uint32_t g_Bfrag[8192];      // E as bf16x2 mma B-fragments
__device__ __align__(16) float    g_P[NCH * NT * NT]; // chunk products
__device__ __align__(16) float    g_Q[NQ * NT * NT];  // folded products (4 chunks each)
__device__ int                    g_kf[NQ];           // fold pow2 scales

// ---------------- helpers ----------------
__device__ __forceinline__ uint32_t pack_bf16x2(float lo, float hi) {
    uint32_t r;
    asm("cvt.rn.bf16x2.f32 %0, %1, %2;" : "=r"(r) : "f"(hi), "f"(lo));
    return r;
}
__device__ __forceinline__ void mma16(float& c0, float& c1, float& c2, float& c3,
                                      uint32_t a0, uint32_t a1, uint32_t a2, uint32_t a3,
                                      uint32_t b0, uint32_t b1) {
    asm volatile("mma.sync.aligned.m16n8k16.row.col.f32.bf16.bf16.f32 "
                 "{%0,%1,%2,%3},{%4,%5,%6,%7},{%8,%9},{%0,%1,%2,%3};"
                 : "+f"(c0), "+f"(c1), "+f"(c2), "+f"(c3)
                 : "r"(a0), "r"(a1), "r"(a2), "r"(a3), "r"(b0), "r"(b1));
}
__device__ __forceinline__ void cp16(void* s, const void* g) {
    uint32_t sa = (uint32_t)__cvta_generic_to_shared(s);
    asm volatile("cp.async.ca.shared.global [%0], [%1], 16;" :: "r"(sa), "l"(g) : "memory");
}
#define CP_COMMIT() asm volatile("cp.async.commit_group;" ::: "memory")
#define CP_WAIT(n)  asm volatile("cp.async.wait_group %0;" :: "n"(n) : "memory")

// ---------------- prep 1: E = exp(T), col sums, B fragments ----------------
__global__ void prep_E(const float* __restrict__ trans) {
    const int j = threadIdx.x;
    float cs = 0.0f;
    for (int k = 0; k < NT; k++) {
        float e = __expf(trans[k * NT + j]);
        g_E[k * NT + j] = e;
        cs += e;
    }
    g_csum[j] = cs;

    const int l = j & 31, m = l & 3, n8 = l >> 2;
    const int ktbase = (j >> 5) * 2;
    for (int kt2 = ktbase; kt2 < ktbase + 2; kt2++)
        for (int nt = 0; nt < 16; nt++) {
            int n = 8 * nt + n8, k0 = 16 * kt2 + 2 * m;
            uint32_t b0 = pack_bf16x2(__expf(trans[(k0)     * NT + n]),
                                      __expf(trans[(k0 + 1) * NT + n]));
            uint32_t b1 = pack_bf16x2(__expf(trans[(k0 + 8) * NT + n]),
                                      __expf(trans[(k0 + 9) * NT + n]));
            int idx = ((kt2 * 16 + nt) * 32 + l) * 2;
            g_Bfrag[idx] = b0;
            g_Bfrag[idx + 1] = b1;
        }
}

// ---------------- prep 2: gather emissions, exp, per-step pow2 scale ----
__global__ void prep_D(const int* __restrict__ x, const float* __restrict__ emit) {
    __shared__ float sw[NT];
    const int t = blockIdx.x, j = threadIdx.x;
    float w = __expf(emit[(long long)x[t + 1] * NT + j]);
    sw[j] = w * g_csum[j];
    __syncthreads();
    for (int off = 64; off; off >>= 1) {
        if (j < off) sw[j] += sw[j + off];
        __syncthreads();
    }
    int kt = (((__float_as_int(sw[0]) >> 23) & 255) - 127) - 7;  // mean rowsum in [1,2)
    g_d[t * NT + j] = ldexpf(w, -kt);
    if (j == 0) g_k[t] = kt;
}

// ---------------- chunk kernel (unchanged, passing) ----------------
__global__ void __launch_bounds__(128, 1) chunk_kernel() {
    __shared__ __align__(16) uint32_t sB[8192];
    __shared__ __align__(16) float    sd[4][2][NT];

    const int tid = threadIdx.x, w = tid >> 5, l = tid & 31, m = l & 3;
    const int c  = blockIdx.x;
    const int t0 = (c * TSTEPS) / NCH;
    const int S  = ((c + 1) * TSTEPS) / NCH - t0;

    {
        const uint4* src = (const uint4*)g_Bfrag;
        uint4* dst = (uint4*)sB;
        for (int i = tid; i < 2048; i += 128) dst[i] = src[i];
    }
    cp16(&sd[w][0][l * 4], &g_d[(size_t)t0 * NT + l * 4]);
    CP_COMMIT();
    CP_WAIT(0);
    __syncwarp();
    __syncthreads();

    float C[2][16][4];
    const int r0 = 32 * w + (l >> 2);
#pragma unroll
    for (int rt = 0; rt < 2; rt++)
#pragma unroll
        for (int nt = 0; nt < 16; nt++) {
            int rr = r0 + 16 * rt, cc = 8 * nt + 2 * m;
            float2 v0 = *(const float2*)&g_E[rr * NT + cc];
            float2 v1 = *(const float2*)&g_E[(rr + 8) * NT + cc];
            C[rt][nt][0] = v0.x; C[rt][nt][1] = v0.y;
            C[rt][nt][2] = v1.x; C[rt][nt][3] = v1.y;
        }

    uint32_t A[2][8][4];
    for (int s = 0; s < S - 1; s++) {
        const int buf = s & 1;
        cp16(&sd[w][buf ^ 1][l * 4], &g_d[(size_t)(t0 + s + 1) * NT + l * 4]);
        CP_COMMIT();
        CP_WAIT(1);
        __syncwarp();

#pragma unroll
        for (int rt = 0; rt < 2; rt++)
#pragma unroll
            for (int kt2 = 0; kt2 < 8; kt2++) {
                float2 dA = *(const float2*)&sd[w][buf][16 * kt2 + 2 * m];
                float2 dB = *(const float2*)&sd[w][buf][16 * kt2 + 2 * m + 8];
                A[rt][kt2][0] = pack_bf16x2(C[rt][2 * kt2][0] * dA.x,     C[rt][2 * kt2][1] * dA.y);
                A[rt][kt2][1] = pack_bf16x2(C[rt][2 * kt2][2] * dA.x,     C[rt][2 * kt2][3] * dA.y);
                A[rt][kt2][2] = pack_bf16x2(C[rt][2 * kt2 + 1][0] * dB.x, C[rt][2 * kt2 + 1][1] * dB.y);
                A[rt][kt2][3] = pack_bf16x2(C[rt][2 * kt2 + 1][2] * dB.x, C[rt][2 * kt2 + 1][3] * dB.y);
            }
#pragma unroll
        for (int rt = 0; rt < 2; rt++)
#pragma unroll
            for (int nt = 0; nt < 16; nt++) {
                C[rt][nt][0] = 0.f; C[rt][nt][1] = 0.f;
                C[rt][nt][2] = 0.f; C[rt][nt][3] = 0.f;
            }
#pragma unroll
        for (int nt = 0; nt < 16; nt++)
#pragma unroll
            for (int kt2 = 0; kt2 < 8; kt2++) {
                uint2 b = *(const uint2*)&sB[((kt2 * 16 + nt) * 32 + l) * 2];
                mma16(C[0][nt][0], C[0][nt][1], C[0][nt][2], C[0][nt][3],
                      A[0][kt2][0], A[0][kt2][1], A[0][kt2][2], A[0][kt2][3], b.x, b.y);
                mma16(C[1][nt][0], C[1][nt][1], C[1][nt][2], C[1][nt][3],
                      A[1][kt2][0], A[1][kt2][1], A[1][kt2][2], A[1][kt2][3], b.x, b.y);
            }
    }

    CP_WAIT(0);
    __syncwarp();
    const int lastbuf = (S - 1) & 1;
    float* Pout = g_P + (size_t)c * NT * NT;
#pragma unroll
    for (int rt = 0; rt < 2; rt++)
#pragma unroll
        for (int nt = 0; nt < 16; nt++) {
            int rr = r0 + 16 * rt, cc = 8 * nt + 2 * m;
            float2 dv = *(const float2*)&sd[w][lastbuf][cc];
            float2 o0 = make_float2(C[rt][nt][0] * dv.x, C[rt][nt][1] * dv.y);
            float2 o1 = make_float2(C[rt][nt][2] * dv.x, C[rt][nt][3] * dv.y);
            *(float2*)&Pout[(size_t)rr * NT + cc]       = o0;
            *(float2*)&Pout[(size_t)(rr + 8) * NT + cc] = o1;
        }
}

// ---------------- fold4: Q_c = P_{4c} x P_{4c+1} x P_{4c+2} x P_{4c+3} ----------------
// 37 CTAs x 128 threads. Same fragment machinery as chunk; B-side renormed to <=1
// by its max exponent (recorded in g_kf). Staging buffer padded to 132 floats/row
// so fragment-build LDS reads are bank-conflict-free (bank = 8m + n8 + const).
#define RAWPITCH 132
__global__ void __launch_bounds__(128, 1) fold4_kernel() {
    extern __shared__ __align__(16) char fsm[];
    float*    sraw = (float*)fsm;                          // 128 x 132 floats
    uint32_t* sB   = (uint32_t*)(fsm + NT * RAWPITCH * 4); // 8192 words
    __shared__ float smax[NT];

    const int tid = threadIdx.x, w = tid >> 5, l = tid & 31, m = l & 3, n8 = l >> 2;
    const int c = blockIdx.x;
    const float* Pin0 = g_P + (size_t)(4 * c) * NT * NT;

    // C init = P_{4c} (fp32, raw) in C-fragment layout
    float C[2][16][4];
    const int r0 = 32 * w + (l >> 2);
#pragma unroll
    for (int rt = 0; rt < 2; rt++)
#pragma unroll
        for (int nt = 0; nt < 16; nt++) {
            int rr = r0 + 16 * rt, cc = 8 * nt + 2 * m;
            float2 v0 = *(const float2*)&Pin0[rr * NT + cc];
            float2 v1 = *(const float2*)&Pin0[(rr + 8) * NT + cc];
            C[rt][nt][0] = v0.x; C[rt][nt][1] = v0.y;
            C[rt][nt][2] = v1.x; C[rt][nt][3] = v1.y;
        }

    int ef = 0;
    uint32_t A[2][8][4];
    for (int s = 1; s < 4; s++) {
        // stage P_{4c+s} into padded SMEM (coalesced cp.async)
        const float* Pin = g_P + (size_t)(4 * c + s) * NT * NT;
        for (int u = tid; u < 4096; u += 128) {
            int row = u >> 5, qq = u & 31;
            cp16(&sraw[row * RAWPITCH + qq * 4], Pin + row * NT + qq * 4);
        }
        CP_COMMIT();
        CP_WAIT(0);
        __syncthreads();

        // max reduce -> power-of-2 scale so scaled B <= 1
        float mx = 0.0f;
        for (int u = tid; u < NT * NT; u += 128)
            mx = fmaxf(mx, sraw[(u >> 7) * RAWPITCH + (u & 127)]);
        smax[tid] = mx;
        __syncthreads();
        for (int off = 64; off; off >>= 1) {
            if (tid < off) smax[tid] = fmaxf(smax[tid], smax[tid + off]);
            __syncthreads();
        }
        int e = (((__float_as_int(smax[0]) >> 23) & 255) - 127) + 1;
        float sc = __int_as_float((uint32_t)(127 - e) << 23);   // exact 2^-e
        ef += e;

        // build bf16 B-fragments (conflict-free thanks to RAWPITCH=132)
#pragma unroll
        for (int kt2 = 2 * w; kt2 < 2 * w + 2; kt2++)
#pragma unroll
            for (int nt = 0; nt < 16; nt++) {
                int k0 = 16 * kt2 + 2 * m, n = 8 * nt + n8;
                float b00 = sraw[(k0)     * RAWPITCH + n] * sc;
                float b01 = sraw[(k0 + 1) * RAWPITCH + n] * sc;
                float b10 = sraw[(k0 + 8) * RAWPITCH + n] * sc;
                float b11 = sraw[(k0 + 9) * RAWPITCH + n] * sc;
                int idx = ((kt2 * 16 + nt) * 32 + l) * 2;
                sB[idx]     = pack_bf16x2(b00, b01);
                sB[idx + 1] = pack_bf16x2(b10, b11);
            }
        __syncthreads();

        // A = bf16(C), no diag
#pragma unroll
        for (int rt = 0; rt < 2; rt++)
#pragma unroll
            for (int kt2 = 0; kt2 < 8; kt2++) {
                A[rt][kt2][0] = pack_bf16x2(C[rt][2 * kt2][0],     C[rt][2 * kt2][1]);
                A[rt][kt2][1] = pack_bf16x2(C[rt][2 * kt2][2],     C[rt][2 * kt2][3]);
                A[rt][kt2][2] = pack_bf16x2(C[rt][2 * kt2 + 1][0], C[rt][2 * kt2 + 1][1]);
                A[rt][kt2][3] = pack_bf16x2(C[rt][2 * kt2 + 1][2], C[rt][2 * kt2 + 1][3]);
            }
#pragma unroll
        for (int rt = 0; rt < 2; rt++)
#pragma unroll
            for (int nt = 0; nt < 16; nt++) {
                C[rt][nt][0] = 0.f; C[rt][nt][1] = 0.f;
                C[rt][nt][2] = 0.f; C[rt][nt][3] = 0.f;
            }
#pragma unroll
        for (int nt = 0; nt < 16; nt++)
#pragma unroll
            for (int kt2 = 0; kt2 < 8; kt2++) {
                uint2 b = *(const uint2*)&sB[((kt2 * 16 + nt) * 32 + l) * 2];
                mma16(C[0][nt][0], C[0][nt][1], C[0][nt][2], C[0][nt][3],
                      A[0][kt2][0], A[0][kt2][1], A[0][kt2][2], A[0][kt2][3], b.x, b.y);
                mma16(C[1][nt][0], C[1][nt][1], C[1][nt][2], C[1][nt][3],
                      A[1][kt2][0], A[1][kt2][1], A[1][kt2][2], A[1][kt2][3], b.x, b.y);
            }
        __syncthreads();   // mma done before sraw/sB overwritten next s
    }

    float* Qout = g_Q + (size_t)c * NT * NT;
#pragma unroll
    for (int rt = 0; rt < 2; rt++)
#pragma unroll
        for (int nt = 0; nt < 16; nt++) {
            int rr = r0 + 16 * rt, cc = 8 * nt + 2 * m;
            *(float2*)&Qout[(size_t)rr * NT + cc]       = make_float2(C[rt][nt][0], C[rt][nt][1]);
            *(float2*)&Qout[(size_t)(rr + 8) * NT + cc] = make_float2(C[rt][nt][2], C[rt][nt][3]);
        }
    if (tid == 0) g_kf[c] = ef;
}

// ---------------- combine: chain of 37 matvecs, SMEM double-buffered ----------------
__global__ void __launch_bounds__(512, 1)
combine_kernel(const float* __restrict__ trans, float* __restrict__ out) {
    extern __shared__ __align__(16) float sQ[];   // 2 x 16384 floats
    __shared__ float w[NT];
    __shared__ float part[4][NT];
    __shared__ unsigned long long ks;
    const int tid = threadIdx.x, q = tid >> 7, j = tid & 127;

    long long kl = 0;
    for (int t = tid; t < TSTEPS; t += 512) kl += g_k[t];
    for (int t = tid; t < NQ; t += 512) kl += g_kf[t];
    if (tid == 0) ks = 0ull;
    if (q == 0) w[j] = (j == 0) ? 1.0f : 0.0f;
    __syncthreads();
    atomicAdd(&ks, (unsigned long long)kl);

#define PREF(buf, cc) do {                                                         \
        const float* _src = g_Q + (size_t)(cc) * NT * NT;                          \
        for (int v = 0; v < 8; v++) {                                              \
            int i = tid + 512 * v;                                                 \
            cp16(&sQ[(buf) * 16384 + i * 4], _src + i * 4);                        \
        }                                                                          \
        CP_COMMIT();                                                               \
    } while (0)

    PREF(0, 0);

    long long Kacc = 0;
    for (int cc = 0; cc < NQ; cc++) {
        const int buf = cc & 1;
        if (cc < NQ - 1) { PREF(buf ^ 1, cc + 1); CP_WAIT(1); }
        else             { CP_WAIT(0); }
        __syncthreads();                       // all threads' tiles visible

        const float* P = &sQ[buf * 16384];
        float acc = 0.0f;
        const int k0 = 32 * q;
#pragma unroll
        for (int k = k0; k < k0 + 32; k++) acc = fmaf(w[k], P[k * NT + j], acc);
        part[q][j] = acc;
        __syncthreads();

        float red  = part[0][j] + part[1][j] + part[2][j] + part[3][j];
        float red0 = part[0][0] + part[1][0] + part[2][0] + part[3][0];
        int k2 = ((__float_as_int(red0) >> 23) & 255) - 127;
        Kacc += k2;
        if (q == 0) w[j] = ldexpf(red, -k2);
        __syncthreads();
    }

    if (tid == 0) {
        float sum = 0.0f;
        for (int i = 0; i < NT; i++) sum += w[i] * __expf(trans[i * NT + 1]);  // END=1
        double z = (double)((long long)ks + Kacc) * 0.6931471805599453 +
                   log((double)sum);
        out[0] = (float)z;
    }
}

// ---------------- launch ----------------
extern "C" void kernel_launch(void* const* d_in, const int* in_sizes, int n_in,
                              void* d_out, int out_size) {
    const int* x = nullptr;
    const float* emit = nullptr;
    const float* trans = nullptr;
    for (int i = 0; i < n_in; i++) {
        if (in_sizes[i] == 8192)         x     = (const int*)d_in[i];
        else if (in_sizes[i] == NT * NT) trans = (const float*)d_in[i];
        else                             emit  = (const float*)d_in[i];
    }
    float* out = (float*)d_out;

    const int FOLD_SMEM = NT * RAWPITCH * 4 + 8192 * 4;   // 67584 + 32768 = 100352
    const int COMB_SMEM = 2 * NT * NT * 4;                // 131072
    cudaFuncSetAttribute(fold4_kernel,  cudaFuncAttributeMaxDynamicSharedMemorySize, FOLD_SMEM);
    cudaFuncSetAttribute(combine_kernel, cudaFuncAttributeMaxDynamicSharedMemorySize, COMB_SMEM);

    prep_E<<<1, NT>>>(trans);
    prep_D<<<TSTEPS, NT>>>(x, emit);
    chunk_kernel<<<NCH, 128>>>();
    fold4_kernel<<<NQ, 128, FOLD_SMEM>>>();
    combine_kernel<<<1, 512, COMB_SMEM>>>(trans, out);
}

// round 13
// speedup vs baseline: 1.0076x; 1.0017x over previous
#include <cuda_runtime.h>
#include <cuda_bf16.h>
#include <cstdint>

#define NT     128
#define TSTEPS 8191
#define NCH    148
#define NQ     37          // NCH / 4

// ---------------- global scratch (static) ----------------
__device__ __align__(16) float    g_E[NT * NT];       // exp(T), fp32
__device__ float                  g_csum[NT];         // col sums of exp(T)
__device__ __align__(16) float    g_d[TSTEPS * NT];   // exp(emit)*2^-k_t, scaled
__device__ int                    g_k[TSTEPS];        // per-step pow2 scales
__device__ __align__(16) uint32_t g_Bfrag[8192];      // E as bf16x2 mma B-fragments
__device__ __align__(16) float    g_P[NCH * NT * NT]; // chunk products
__device__ __align__(16) float    g_Q[NQ * NT * NT];  // folded products (4 chunks each)
__device__ int                    g_kf[NQ];           // fold pow2 scales

// ---------------- helpers ----------------
__device__ __forceinline__ uint32_t pack_bf16x2(float lo, float hi) {
    uint32_t r;
    asm("cvt.rn.bf16x2.f32 %0, %1, %2;" : "=r"(r) : "f"(hi), "f"(lo));
    return r;
}
__device__ __forceinline__ void mma16(float& c0, float& c1, float& c2, float& c3,
                                      uint32_t a0, uint32_t a1, uint32_t a2, uint32_t a3,
                                      uint32_t b0, uint32_t b1) {
    asm volatile("mma.sync.aligned.m16n8k16.row.col.f32.bf16.bf16.f32 "
                 "{%0,%1,%2,%3},{%4,%5,%6,%7},{%8,%9},{%0,%1,%2,%3};"
                 : "+f"(c0), "+f"(c1), "+f"(c2), "+f"(c3)
                 : "r"(a0), "r"(a1), "r"(a2), "r"(a3), "r"(b0), "r"(b1));
}
__device__ __forceinline__ void cp16(void* s, const void* g) {
    uint32_t sa = (uint32_t)__cvta_generic_to_shared(s);
    asm volatile("cp.async.ca.shared.global [%0], [%1], 16;" :: "r"(sa), "l"(g) : "memory");
}
#define CP_COMMIT() asm volatile("cp.async.commit_group;" ::: "memory")
#define CP_WAIT(n)  asm volatile("cp.async.wait_group %0;" :: "n"(n) : "memory")

// ---------------- prep 1: E = exp(T), col sums, B fragments ----------------
__global__ void prep_E(const float* __restrict__ trans) {
    const int j = threadIdx.x;
    float cs = 0.0f;
    for (int k = 0; k < NT; k++) {
        float e = __expf(trans[k * NT + j]);
        g_E[k * NT + j] = e;
        cs += e;
    }
    g_csum[j] = cs;

    const int l = j & 31, m = l & 3, n8 = l >> 2;
    const int ktbase = (j >> 5) * 2;
    for (int kt2 = ktbase; kt2 < ktbase + 2; kt2++)
        for (int nt = 0; nt < 16; nt++) {
            int n = 8 * nt + n8, k0 = 16 * kt2 + 2 * m;
            uint32_t b0 = pack_bf16x2(__expf(trans[(k0)     * NT + n]),
                                      __expf(trans[(k0 + 1) * NT + n]));
            uint32_t b1 = pack_bf16x2(__expf(trans[(k0 + 8) * NT + n]),
                                      __expf(trans[(k0 + 9) * NT + n]));
            int idx = ((kt2 * 16 + nt) * 32 + l) * 2;
            g_Bfrag[idx] = b0;
            g_Bfrag[idx + 1] = b1;
        }
}

// ---------------- prep 2: gather emissions, exp, per-step pow2 scale ----
__global__ void prep_D(const int* __restrict__ x, const float* __restrict__ emit) {
    __shared__ float sw[NT];
    const int t = blockIdx.x, j = threadIdx.x;
    float w = __expf(emit[(long long)x[t + 1] * NT + j]);
    sw[j] = w * g_csum[j];
    __syncthreads();
    for (int off = 64; off; off >>= 1) {
        if (j < off) sw[j] += sw[j + off];
        __syncthreads();
    }
    int kt = (((__float_as_int(sw[0]) >> 23) & 255) - 127) - 7;  // mean rowsum in [1,2)
    g_d[t * NT + j] = ldexpf(w, -kt);
    if (j == 0) g_k[t] = kt;
}

// ---------------- chunk kernel (unchanged, passing) ----------------
__global__ void __launch_bounds__(128, 1) chunk_kernel() {
    __shared__ __align__(16) uint32_t sB[8192];
    __shared__ __align__(16) float    sd[4][2][NT];

    const int tid = threadIdx.x, w = tid >> 5, l = tid & 31, m = l & 3;
    const int c  = blockIdx.x;
    const int t0 = (c * TSTEPS) / NCH;
    const int S  = ((c + 1) * TSTEPS) / NCH - t0;

    {
        const uint4* src = (const uint4*)g_Bfrag;
        uint4* dst = (uint4*)sB;
        for (int i = tid; i < 2048; i += 128) dst[i] = src[i];
    }
    cp16(&sd[w][0][l * 4], &g_d[(size_t)t0 * NT + l * 4]);
    CP_COMMIT();
    CP_WAIT(0);
    __syncwarp();
    __syncthreads();

    float C[2][16][4];
    const int r0 = 32 * w + (l >> 2);
#pragma unroll
    for (int rt = 0; rt < 2; rt++)
#pragma unroll
        for (int nt = 0; nt < 16; nt++) {
            int rr = r0 + 16 * rt, cc = 8 * nt + 2 * m;
            float2 v0 = *(const float2*)&g_E[rr * NT + cc];
            float2 v1 = *(const float2*)&g_E[(rr + 8) * NT + cc];
            C[rt][nt][0] = v0.x; C[rt][nt][1] = v0.y;
            C[rt][nt][2] = v1.x; C[rt][nt][3] = v1.y;
        }

    uint32_t A[2][8][4];
    for (int s = 0; s < S - 1; s++) {
        const int buf = s & 1;
        cp16(&sd[w][buf ^ 1][l * 4], &g_d[(size_t)(t0 + s + 1) * NT + l * 4]);
        CP_COMMIT();
        CP_WAIT(1);
        __syncwarp();

#pragma unroll
        for (int rt = 0; rt < 2; rt++)
#pragma unroll
            for (int kt2 = 0; kt2 < 8; kt2++) {
                float2 dA = *(const float2*)&sd[w][buf][16 * kt2 + 2 * m];
                float2 dB = *(const float2*)&sd[w][buf][16 * kt2 + 2 * m + 8];
                A[rt][kt2][0] = pack_bf16x2(C[rt][2 * kt2][0] * dA.x,     C[rt][2 * kt2][1] * dA.y);
                A[rt][kt2][1] = pack_bf16x2(C[rt][2 * kt2][2] * dA.x,     C[rt][2 * kt2][3] * dA.y);
                A[rt][kt2][2] = pack_bf16x2(C[rt][2 * kt2 + 1][0] * dB.x, C[rt][2 * kt2 + 1][1] * dB.y);
                A[rt][kt2][3] = pack_bf16x2(C[rt][2 * kt2 + 1][2] * dB.x, C[rt][2 * kt2 + 1][3] * dB.y);
            }
#pragma unroll
        for (int rt = 0; rt < 2; rt++)
#pragma unroll
            for (int nt = 0; nt < 16; nt++) {
                C[rt][nt][0] = 0.f; C[rt][nt][1] = 0.f;
                C[rt][nt][2] = 0.f; C[rt][nt][3] = 0.f;
            }
#pragma unroll
        for (int nt = 0; nt < 16; nt++)
#pragma unroll
            for (int kt2 = 0; kt2 < 8; kt2++) {
                uint2 b = *(const uint2*)&sB[((kt2 * 16 + nt) * 32 + l) * 2];
                mma16(C[0][nt][0], C[0][nt][1], C[0][nt][2], C[0][nt][3],
                      A[0][kt2][0], A[0][kt2][1], A[0][kt2][2], A[0][kt2][3], b.x, b.y);
                mma16(C[1][nt][0], C[1][nt][1], C[1][nt][2], C[1][nt][3],
                      A[1][kt2][0], A[1][kt2][1], A[1][kt2][2], A[1][kt2][3], b.x, b.y);
            }
    }

    CP_WAIT(0);
    __syncwarp();
    const int lastbuf = (S - 1) & 1;
    float* Pout = g_P + (size_t)c * NT * NT;
#pragma unroll
    for (int rt = 0; rt < 2; rt++)
#pragma unroll
        for (int nt = 0; nt < 16; nt++) {
            int rr = r0 + 16 * rt, cc = 8 * nt + 2 * m;
            float2 dv = *(const float2*)&sd[w][lastbuf][cc];
            float2 o0 = make_float2(C[rt][nt][0] * dv.x, C[rt][nt][1] * dv.y);
            float2 o1 = make_float2(C[rt][nt][2] * dv.x, C[rt][nt][3] * dv.y);
            *(float2*)&Pout[(size_t)rr * NT + cc]       = o0;
            *(float2*)&Pout[(size_t)(rr + 8) * NT + cc] = o1;
        }
}

// ---------------- fold4: Q_c = P_{4c} x P_{4c+1} x P_{4c+2} x P_{4c+3} ----------------
// 37 CTAs x 128 threads. Same fragment machinery as chunk; B-side renormed to <=1
// by its max exponent (recorded in g_kf). Staging buffer padded to 132 floats/row
// so fragment-build LDS reads are bank-conflict-free (bank = 8m + n8 + const).
#define RAWPITCH 132
__global__ void __launch_bounds__(128, 1) fold4_kernel() {
    extern __shared__ __align__(16) char fsm[];
    float*    sraw = (float*)fsm;                          // 128 x 132 floats
    uint32_t* sB   = (uint32_t*)(fsm + NT * RAWPITCH * 4); // 8192 words
    __shared__ float smax[NT];

    const int tid = threadIdx.x, w = tid >> 5, l = tid & 31, m = l & 3, n8 = l >> 2;
    const int c = blockIdx.x;
    const float* Pin0 = g_P + (size_t)(4 * c) * NT * NT;

    // C init = P_{4c} (fp32, raw) in C-fragment layout
    float C[2][16][4];
    const int r0 = 32 * w + (l >> 2);
#pragma unroll
    for (int rt = 0; rt < 2; rt++)
#pragma unroll
        for (int nt = 0; nt < 16; nt++) {
            int rr = r0 + 16 * rt, cc = 8 * nt + 2 * m;
            float2 v0 = *(const float2*)&Pin0[rr * NT + cc];
            float2 v1 = *(const float2*)&Pin0[(rr + 8) * NT + cc];
            C[rt][nt][0] = v0.x; C[rt][nt][1] = v0.y;
            C[rt][nt][2] = v1.x; C[rt][nt][3] = v1.y;
        }

    int ef = 0;
    uint32_t A[2][8][4];
    for (int s = 1; s < 4; s++) {
        // stage P_{4c+s} into padded SMEM (coalesced cp.async)
        const float* Pin = g_P + (size_t)(4 * c + s) * NT * NT;
        for (int u = tid; u < 4096; u += 128) {
            int row = u >> 5, qq = u & 31;
            cp16(&sraw[row * RAWPITCH + qq * 4], Pin + row * NT + qq * 4);
        }
        CP_COMMIT();
        CP_WAIT(0);
        __syncthreads();

        // max reduce -> power-of-2 scale so scaled B <= 1
        float mx = 0.0f;
        for (int u = tid; u < NT * NT; u += 128)
            mx = fmaxf(mx, sraw[(u >> 7) * RAWPITCH + (u & 127)]);
        smax[tid] = mx;
        __syncthreads();
        for (int off = 64; off; off >>= 1) {
            if (tid < off) smax[tid] = fmaxf(smax[tid], smax[tid + off]);
            __syncthreads();
        }
        int e = (((__float_as_int(smax[0]) >> 23) & 255) - 127) + 1;
        float sc = __int_as_float((uint32_t)(127 - e) << 23);   // exact 2^-e
        ef += e;

        // build bf16 B-fragments (conflict-free thanks to RAWPITCH=132)
#pragma unroll
        for (int kt2 = 2 * w; kt2 < 2 * w + 2; kt2++)
#pragma unroll
            for (int nt = 0; nt < 16; nt++) {
                int k0 = 16 * kt2 + 2 * m, n = 8 * nt + n8;
                float b00 = sraw[(k0)     * RAWPITCH + n] * sc;
                float b01 = sraw[(k0 + 1) * RAWPITCH + n] * sc;
                float b10 = sraw[(k0 + 8) * RAWPITCH + n] * sc;
                float b11 = sraw[(k0 + 9) * RAWPITCH + n] * sc;
                int idx = ((kt2 * 16 + nt) * 32 + l) * 2;
                sB[idx]     = pack_bf16x2(b00, b01);
                sB[idx + 1] = pack_bf16x2(b10, b11);
            }
        __syncthreads();

        // A = bf16(C), no diag
#pragma unroll
        for (int rt = 0; rt < 2; rt++)
#pragma unroll
            for (int kt2 = 0; kt2 < 8; kt2++) {
                A[rt][kt2][0] = pack_bf16x2(C[rt][2 * kt2][0],     C[rt][2 * kt2][1]);
                A[rt][kt2][1] = pack_bf16x2(C[rt][2 * kt2][2],     C[rt][2 * kt2][3]);
                A[rt][kt2][2] = pack_bf16x2(C[rt][2 * kt2 + 1][0], C[rt][2 * kt2 + 1][1]);
                A[rt][kt2][3] = pack_bf16x2(C[rt][2 * kt2 + 1][2], C[rt][2 * kt2 + 1][3]);
            }
#pragma unroll
        for (int rt = 0; rt < 2; rt++)
#pragma unroll
            for (int nt = 0; nt < 16; nt++) {
                C[rt][nt][0] = 0.f; C[rt][nt][1] = 0.f;
                C[rt][nt][2] = 0.f; C[rt][nt][3] = 0.f;
            }
#pragma unroll
        for (int nt = 0; nt < 16; nt++)
#pragma unroll
            for (int kt2 = 0; kt2 < 8; kt2++) {
                uint2 b = *(const uint2*)&sB[((kt2 * 16 + nt) * 32 + l) * 2];
                mma16(C[0][nt][0], C[0][nt][1], C[0][nt][2], C[0][nt][3],
                      A[0][kt2][0], A[0][kt2][1], A[0][kt2][2], A[0][kt2][3], b.x, b.y);
                mma16(C[1][nt][0], C[1][nt][1], C[1][nt][2], C[1][nt][3],
                      A[1][kt2][0], A[1][kt2][1], A[1][kt2][2], A[1][kt2][3], b.x, b.y);
            }
        __syncthreads();   // mma done before sraw/sB overwritten next s
    }

    float* Qout = g_Q + (size_t)c * NT * NT;
#pragma unroll
    for (int rt = 0; rt < 2; rt++)
#pragma unroll
        for (int nt = 0; nt < 16; nt++) {
            int rr = r0 + 16 * rt, cc = 8 * nt + 2 * m;
            *(float2*)&Qout[(size_t)rr * NT + cc]       = make_float2(C[rt][nt][0], C[rt][nt][1]);
            *(float2*)&Qout[(size_t)(rr + 8) * NT + cc] = make_float2(C[rt][nt][2], C[rt][nt][3]);
        }
    if (tid == 0) g_kf[c] = ef;
}

// ---------------- combine: chain of 37 matvecs, SMEM double-buffered ----------------
__global__ void __launch_bounds__(512, 1)
combine_kernel(const float* __restrict__ trans, float* __restrict__ out) {
    extern __shared__ __align__(16) float sQ[];   // 2 x 16384 floats
    __shared__ float w[NT];
    __shared__ float part[4][NT];
    __shared__ unsigned long long ks;
    const int tid = threadIdx.x, q = tid >> 7, j = tid & 127;

    long long kl = 0;
    for (int t = tid; t < TSTEPS; t += 512) kl += g_k[t];
    for (int t = tid; t < NQ; t += 512) kl += g_kf[t];
    if (tid == 0) ks = 0ull;
    if (q == 0) w[j] = (j == 0) ? 1.0f : 0.0f;
    __syncthreads();
    atomicAdd(&ks, (unsigned long long)kl);

#define PREF(buf, cc) do {                                                         \
        const float* _src = g_Q + (size_t)(cc) * NT * NT;                          \
        for (int v = 0; v < 8; v++) {                                              \
            int i = tid + 512 * v;                                                 \
            cp16(&sQ[(buf) * 16384 + i * 4], _src + i * 4);                        \
        }                                                                          \
        CP_COMMIT();                                                               \
    } while (0)

    PREF(0, 0);

    long long Kacc = 0;
    for (int cc = 0; cc < NQ; cc++) {
        const int buf = cc & 1;
        if (cc < NQ - 1) { PREF(buf ^ 1, cc + 1); CP_WAIT(1); }
        else             { CP_WAIT(0); }
        __syncthreads();                       // all threads' tiles visible

        const float* P = &sQ[buf * 16384];
        float acc = 0.0f;
        const int k0 = 32 * q;
#pragma unroll
        for (int k = k0; k < k0 + 32; k++) acc = fmaf(w[k], P[k * NT + j], acc);
        part[q][j] = acc;
        __syncthreads();

        float red  = part[0][j] + part[1][j] + part[2][j] + part[3][j];
        float red0 = part[0][0] + part[1][0] + part[2][0] + part[3][0];
        int k2 = ((__float_as_int(red0) >> 23) & 255) - 127;
        Kacc += k2;
        if (q == 0) w[j] = ldexpf(red, -k2);
        __syncthreads();
    }

    if (tid == 0) {
        float sum = 0.0f;
        for (int i = 0; i < NT; i++) sum += w[i] * __expf(trans[i * NT + 1]);  // END=1
        double z = (double)((long long)ks + Kacc) * 0.6931471805599453 +
                   log((double)sum);
        out[0] = (float)z;
    }
}

// ---------------- launch ----------------
extern "C" void kernel_launch(void* const* d_in, const int* in_sizes, int n_in,
                              void* d_out, int out_size) {
    const int* x = nullptr;
    const float* emit = nullptr;
    const float* trans = nullptr;
    for (int i = 0; i < n_in; i++) {
        if (in_sizes[i] == 8192)         x     = (const int*)d_in[i];
        else if (in_sizes[i] == NT * NT) trans = (const float*)d_in[i];
        else                             emit  = (const float*)d_in[i];
    }
    float* out = (float*)d_out;

    const int FOLD_SMEM = NT * RAWPITCH * 4 + 8192 * 4;   // 67584 + 32768 = 100352
    const int COMB_SMEM = 2 * NT * NT * 4;                // 131072
    cudaFuncSetAttribute(fold4_kernel,  cudaFuncAttributeMaxDynamicSharedMemorySize, FOLD_SMEM);
    cudaFuncSetAttribute(combine_kernel, cudaFuncAttributeMaxDynamicSharedMemorySize, COMB_SMEM);

    prep_E<<<1, NT>>>(trans);
    prep_D<<<TSTEPS, NT>>>(x, emit);
    chunk_kernel<<<NCH, 128>>>();
    fold4_kernel<<<NQ, 128, FOLD_SMEM>>>();
    combine_kernel<<<1, 512, COMB_SMEM>>>(trans, out);
}

// round 14
// speedup vs baseline: 1.0093x; 1.0017x over previous
#include <cuda_runtime.h>
#include <cuda_bf16.h>
#include <cstdint>

#define NT     128
#define TSTEPS 8191
#define NCH    148
#define NQ     37          // NCH / 4

// ---------------- global scratch (static) ----------------
__device__ __align__(16) float    g_E[NT * NT];       // exp(T), fp32
__device__ float                  g_csum[NT];         // col sums of exp(T)
__device__ __align__(16) float    g_d[TSTEPS * NT];   // exp(emit)*2^-k_t, scaled
__device__ int                    g_k[TSTEPS];        // per-step pow2 scales
__device__ __align__(16) uint32_t g_Bfrag[8192];      // E as bf16x2 mma B-fragments
__device__ __align__(16) float    g_P[NCH * NT * NT]; // chunk products
__device__ __align__(16) float    g_Q[NQ * NT * NT];  // folded products (4 chunks each)
__device__ int                    g_kf[NQ];           // fold pow2 scales

// ---------------- helpers ----------------
__device__ __forceinline__ uint32_t pack_bf16x2(float lo, float hi) {
    uint32_t r;
    asm("cvt.rn.bf16x2.f32 %0, %1, %2;" : "=r"(r) : "f"(hi), "f"(lo));
    return r;
}
__device__ __forceinline__ void mma16(float& c0, float& c1, float& c2, float& c3,
                                      uint32_t a0, uint32_t a1, uint32_t a2, uint32_t a3,
                                      uint32_t b0, uint32_t b1) {
    asm volatile("mma.sync.aligned.m16n8k16.row.col.f32.bf16.bf16.f32 "
                 "{%0,%1,%2,%3},{%4,%5,%6,%7},{%8,%9},{%0,%1,%2,%3};"
                 : "+f"(c0), "+f"(c1), "+f"(c2), "+f"(c3)
                 : "r"(a0), "r"(a1), "r"(a2), "r"(a3), "r"(b0), "r"(b1));
}
__device__ __forceinline__ void cp16(void* s, const void* g) {
    uint32_t sa = (uint32_t)__cvta_generic_to_shared(s);
    asm volatile("cp.async.ca.shared.global [%0], [%1], 16;" :: "r"(sa), "l"(g) : "memory");
}
#define CP_COMMIT() asm volatile("cp.async.commit_group;" ::: "memory")
#define CP_WAIT(n)  asm volatile("cp.async.wait_group %0;" :: "n"(n) : "memory")

// ---------------- prep 1: E = exp(T), col sums, B fragments ----------------
__global__ void prep_E(const float* __restrict__ trans) {
    const int j = threadIdx.x;
    float cs = 0.0f;
    for (int k = 0; k < NT; k++) {
        float e = __expf(trans[k * NT + j]);
        g_E[k * NT + j] = e;
        cs += e;
    }
    g_csum[j] = cs;

    const int l = j & 31, m = l & 3, n8 = l >> 2;
    const int ktbase = (j >> 5) * 2;
    for (int kt2 = ktbase; kt2 < ktbase + 2; kt2++)
        for (int nt = 0; nt < 16; nt++) {
            int n = 8 * nt + n8, k0 = 16 * kt2 + 2 * m;
            uint32_t b0 = pack_bf16x2(__expf(trans[(k0)     * NT + n]),
                                      __expf(trans[(k0 + 1) * NT + n]));
            uint32_t b1 = pack_bf16x2(__expf(trans[(k0 + 8) * NT + n]),
                                      __expf(trans[(k0 + 9) * NT + n]));
            int idx = ((kt2 * 16 + nt) * 32 + l) * 2;
            g_Bfrag[idx] = b0;
            g_Bfrag[idx + 1] = b1;
        }
}

// ---------------- prep 2: gather emissions, exp, per-step pow2 scale ----
__global__ void prep_D(const int* __restrict__ x, const float* __restrict__ emit) {
    __shared__ float sw[NT];
    const int t = blockIdx.x, j = threadIdx.x;
    float w = __expf(emit[(long long)x[t + 1] * NT + j]);
    sw[j] = w * g_csum[j];
    __syncthreads();
    for (int off = 64; off; off >>= 1) {
        if (j < off) sw[j] += sw[j + off];
        __syncthreads();
    }
    int kt = (((__float_as_int(sw[0]) >> 23) & 255) - 127) - 7;  // mean rowsum in [1,2)
    g_d[t * NT + j] = ldexpf(w, -kt);
    if (j == 0) g_k[t] = kt;
}

// ---------------- chunk kernel (unchanged, passing) ----------------
__global__ void __launch_bounds__(128, 1) chunk_kernel() {
    __shared__ __align__(16) uint32_t sB[8192];
    __shared__ __align__(16) float    sd[4][2][NT];

    const int tid = threadIdx.x, w = tid >> 5, l = tid & 31, m = l & 3;
    const int c  = blockIdx.x;
    const int t0 = (c * TSTEPS) / NCH;
    const int S  = ((c + 1) * TSTEPS) / NCH - t0;

    {
        const uint4* src = (const uint4*)g_Bfrag;
        uint4* dst = (uint4*)sB;
        for (int i = tid; i < 2048; i += 128) dst[i] = src[i];
    }
    cp16(&sd[w][0][l * 4], &g_d[(size_t)t0 * NT + l * 4]);
    CP_COMMIT();
    CP_WAIT(0);
    __syncwarp();
    __syncthreads();

    float C[2][16][4];
    const int r0 = 32 * w + (l >> 2);
#pragma unroll
    for (int rt = 0; rt < 2; rt++)
#pragma unroll
        for (int nt = 0; nt < 16; nt++) {
            int rr = r0 + 16 * rt, cc = 8 * nt + 2 * m;
            float2 v0 = *(const float2*)&g_E[rr * NT + cc];
            float2 v1 = *(const float2*)&g_E[(rr + 8) * NT + cc];
            C[rt][nt][0] = v0.x; C[rt][nt][1] = v0.y;
            C[rt][nt][2] = v1.x; C[rt][nt][3] = v1.y;
        }

    uint32_t A[2][8][4];
    for (int s = 0; s < S - 1; s++) {
        const int buf = s & 1;
        cp16(&sd[w][buf ^ 1][l * 4], &g_d[(size_t)(t0 + s + 1) * NT + l * 4]);
        CP_COMMIT();
        CP_WAIT(1);
        __syncwarp();

#pragma unroll
        for (int rt = 0; rt < 2; rt++)
#pragma unroll
            for (int kt2 = 0; kt2 < 8; kt2++) {
                float2 dA = *(const float2*)&sd[w][buf][16 * kt2 + 2 * m];
                float2 dB = *(const float2*)&sd[w][buf][16 * kt2 + 2 * m + 8];
                A[rt][kt2][0] = pack_bf16x2(C[rt][2 * kt2][0] * dA.x,     C[rt][2 * kt2][1] * dA.y);
                A[rt][kt2][1] = pack_bf16x2(C[rt][2 * kt2][2] * dA.x,     C[rt][2 * kt2][3] * dA.y);
                A[rt][kt2][2] = pack_bf16x2(C[rt][2 * kt2 + 1][0] * dB.x, C[rt][2 * kt2 + 1][1] * dB.y);
                A[rt][kt2][3] = pack_bf16x2(C[rt][2 * kt2 + 1][2] * dB.x, C[rt][2 * kt2 + 1][3] * dB.y);
            }
#pragma unroll
        for (int rt = 0; rt < 2; rt++)
#pragma unroll
            for (int nt = 0; nt < 16; nt++) {
                C[rt][nt][0] = 0.f; C[rt][nt][1] = 0.f;
                C[rt][nt][2] = 0.f; C[rt][nt][3] = 0.f;
            }
#pragma unroll
        for (int nt = 0; nt < 16; nt++)
#pragma unroll
            for (int kt2 = 0; kt2 < 8; kt2++) {
                uint2 b = *(const uint2*)&sB[((kt2 * 16 + nt) * 32 + l) * 2];
                mma16(C[0][nt][0], C[0][nt][1], C[0][nt][2], C[0][nt][3],
                      A[0][kt2][0], A[0][kt2][1], A[0][kt2][2], A[0][kt2][3], b.x, b.y);
                mma16(C[1][nt][0], C[1][nt][1], C[1][nt][2], C[1][nt][3],
                      A[1][kt2][0], A[1][kt2][1], A[1][kt2][2], A[1][kt2][3], b.x, b.y);
            }
    }

    CP_WAIT(0);
    __syncwarp();
    const int lastbuf = (S - 1) & 1;
    float* Pout = g_P + (size_t)c * NT * NT;
#pragma unroll
    for (int rt = 0; rt < 2; rt++)
#pragma unroll
        for (int nt = 0; nt < 16; nt++) {
            int rr = r0 + 16 * rt, cc = 8 * nt + 2 * m;
            float2 dv = *(const float2*)&sd[w][lastbuf][cc];
            float2 o0 = make_float2(C[rt][nt][0] * dv.x, C[rt][nt][1] * dv.y);
            float2 o1 = make_float2(C[rt][nt][2] * dv.x, C[rt][nt][3] * dv.y);
            *(float2*)&Pout[(size_t)rr * NT + cc]       = o0;
            *(float2*)&Pout[(size_t)(rr + 8) * NT + cc] = o1;
        }
}

// ---------------- fold4: Q_c = P_{4c} x P_{4c+1} x P_{4c+2} x P_{4c+3} ----------------
// 37 CTAs x 128 threads. Same fragment machinery as chunk; B-side renormed to <=1
// by its max exponent (recorded in g_kf). Staging buffer padded to 132 floats/row
// so fragment-build LDS reads are bank-conflict-free (bank = 8m + n8 + const).
#define RAWPITCH 132
__global__ void __launch_bounds__(128, 1) fold4_kernel() {
    extern __shared__ __align__(16) char fsm[];
    float*    sraw = (float*)fsm;                          // 128 x 132 floats
    uint32_t* sB   = (uint32_t*)(fsm + NT * RAWPITCH * 4); // 8192 words
    __shared__ float smax[NT];

    const int tid = threadIdx.x, w = tid >> 5, l = tid & 31, m = l & 3, n8 = l >> 2;
    const int c = blockIdx.x;
    const float* Pin0 = g_P + (size_t)(4 * c) * NT * NT;

    // C init = P_{4c} (fp32, raw) in C-fragment layout
    float C[2][16][4];
    const int r0 = 32 * w + (l >> 2);
#pragma unroll
    for (int rt = 0; rt < 2; rt++)
#pragma unroll
        for (int nt = 0; nt < 16; nt++) {
            int rr = r0 + 16 * rt, cc = 8 * nt + 2 * m;
            float2 v0 = *(const float2*)&Pin0[rr * NT + cc];
            float2 v1 = *(const float2*)&Pin0[(rr + 8) * NT + cc];
            C[rt][nt][0] = v0.x; C[rt][nt][1] = v0.y;
            C[rt][nt][2] = v1.x; C[rt][nt][3] = v1.y;
        }

    int ef = 0;
    uint32_t A[2][8][4];
    for (int s = 1; s < 4; s++) {
        // stage P_{4c+s} into padded SMEM (coalesced cp.async)
        const float* Pin = g_P + (size_t)(4 * c + s) * NT * NT;
        for (int u = tid; u < 4096; u += 128) {
            int row = u >> 5, qq = u & 31;
            cp16(&sraw[row * RAWPITCH + qq * 4], Pin + row * NT + qq * 4);
        }
        CP_COMMIT();
        CP_WAIT(0);
        __syncthreads();

        // max reduce -> power-of-2 scale so scaled B <= 1
        float mx = 0.0f;
        for (int u = tid; u < NT * NT; u += 128)
            mx = fmaxf(mx, sraw[(u >> 7) * RAWPITCH + (u & 127)]);
        smax[tid] = mx;
        __syncthreads();
        for (int off = 64; off; off >>= 1) {
            if (tid < off) smax[tid] = fmaxf(smax[tid], smax[tid + off]);
            __syncthreads();
        }
        int e = (((__float_as_int(smax[0]) >> 23) & 255) - 127) + 1;
        float sc = __int_as_float((uint32_t)(127 - e) << 23);   // exact 2^-e
        ef += e;

        // build bf16 B-fragments (conflict-free thanks to RAWPITCH=132)
#pragma unroll
        for (int kt2 = 2 * w; kt2 < 2 * w + 2; kt2++)
#pragma unroll
            for (int nt = 0; nt < 16; nt++) {
                int k0 = 16 * kt2 + 2 * m, n = 8 * nt + n8;
                float b00 = sraw[(k0)     * RAWPITCH + n] * sc;
                float b01 = sraw[(k0 + 1) * RAWPITCH + n] * sc;
                float b10 = sraw[(k0 + 8) * RAWPITCH + n] * sc;
                float b11 = sraw[(k0 + 9) * RAWPITCH + n] * sc;
                int idx = ((kt2 * 16 + nt) * 32 + l) * 2;
                sB[idx]     = pack_bf16x2(b00, b01);
                sB[idx + 1] = pack_bf16x2(b10, b11);
            }
        __syncthreads();

        // A = bf16(C), no diag
#pragma unroll
        for (int rt = 0; rt < 2; rt++)
#pragma unroll
            for (int kt2 = 0; kt2 < 8; kt2++) {
                A[rt][kt2][0] = pack_bf16x2(C[rt][2 * kt2][0],     C[rt][2 * kt2][1]);
                A[rt][kt2][1] = pack_bf16x2(C[rt][2 * kt2][2],     C[rt][2 * kt2][3]);
                A[rt][kt2][2] = pack_bf16x2(C[rt][2 * kt2 + 1][0], C[rt][2 * kt2 + 1][1]);
                A[rt][kt2][3] = pack_bf16x2(C[rt][2 * kt2 + 1][2], C[rt][2 * kt2 + 1][3]);
            }
#pragma unroll
        for (int rt = 0; rt < 2; rt++)
#pragma unroll
            for (int nt = 0; nt < 16; nt++) {
                C[rt][nt][0] = 0.f; C[rt][nt][1] = 0.f;
                C[rt][nt][2] = 0.f; C[rt][nt][3] = 0.f;
            }
#pragma unroll
        for (int nt = 0; nt < 16; nt++)
#pragma unroll
            for (int kt2 = 0; kt2 < 8; kt2++) {
                uint2 b = *(const uint2*)&sB[((kt2 * 16 + nt) * 32 + l) * 2];
                mma16(C[0][nt][0], C[0][nt][1], C[0][nt][2], C[0][nt][3],
                      A[0][kt2][0], A[0][kt2][1], A[0][kt2][2], A[0][kt2][3], b.x, b.y);
                mma16(C[1][nt][0], C[1][nt][1], C[1][nt][2], C[1][nt][3],
                      A[1][kt2][0], A[1][kt2][1], A[1][kt2][2], A[1][kt2][3], b.x, b.y);
            }
        __syncthreads();   // mma done before sraw/sB overwritten next s
    }

    float* Qout = g_Q + (size_t)c * NT * NT;
#pragma unroll
    for (int rt = 0; rt < 2; rt++)
#pragma unroll
        for (int nt = 0; nt < 16; nt++) {
            int rr = r0 + 16 * rt, cc = 8 * nt + 2 * m;
            *(float2*)&Qout[(size_t)rr * NT + cc]       = make_float2(C[rt][nt][0], C[rt][nt][1]);
            *(float2*)&Qout[(size_t)(rr + 8) * NT + cc] = make_float2(C[rt][nt][2], C[rt][nt][3]);
        }
    if (tid == 0) g_kf[c] = ef;
}

// ---------------- combine: chain of 37 matvecs, SMEM double-buffered ----------------
__global__ void __launch_bounds__(512, 1)
combine_kernel(const float* __restrict__ trans, float* __restrict__ out) {
    extern __shared__ __align__(16) float sQ[];   // 2 x 16384 floats
    __shared__ float w[NT];
    __shared__ float part[4][NT];
    __shared__ unsigned long long ks;
    const int tid = threadIdx.x, q = tid >> 7, j = tid & 127;

    long long kl = 0;
    for (int t = tid; t < TSTEPS; t += 512) kl += g_k[t];
    for (int t = tid; t < NQ; t += 512) kl += g_kf[t];
    if (tid == 0) ks = 0ull;
    if (q == 0) w[j] = (j == 0) ? 1.0f : 0.0f;
    __syncthreads();
    atomicAdd(&ks, (unsigned long long)kl);

#define PREF(buf, cc) do {                                                         \
        const float* _src = g_Q + (size_t)(cc) * NT * NT;                          \
        for (int v = 0; v < 8; v++) {                                              \
            int i = tid + 512 * v;                                                 \
            cp16(&sQ[(buf) * 16384 + i * 4], _src + i * 4);                        \
        }                                                                          \
        CP_COMMIT();                                                               \
    } while (0)

    PREF(0, 0);

    long long Kacc = 0;
    for (int cc = 0; cc < NQ; cc++) {
        const int buf = cc & 1;
        if (cc < NQ - 1) { PREF(buf ^ 1, cc + 1); CP_WAIT(1); }
        else             { CP_WAIT(0); }
        __syncthreads();                       // all threads' tiles visible

        const float* P = &sQ[buf * 16384];
        float acc = 0.0f;
        const int k0 = 32 * q;
#pragma unroll
        for (int k = k0; k < k0 + 32; k++) acc = fmaf(w[k], P[k * NT + j], acc);
        part[q][j] = acc;
        __syncthreads();

        float red  = part[0][j] + part[1][j] + part[2][j] + part[3][j];
        float red0 = part[0][0] + part[1][0] + part[2][0] + part[3][0];
        int k2 = ((__float_as_int(red0) >> 23) & 255) - 127;
        Kacc += k2;
        if (q == 0) w[j] = ldexpf(red, -k2);
        __syncthreads();
    }

    if (tid == 0) {
        float sum = 0.0f;
        for (int i = 0; i < NT; i++) sum += w[i] * __expf(trans[i * NT + 1]);  // END=1
        double z = (double)((long long)ks + Kacc) * 0.6931471805599453 +
                   log((double)sum);
        out[0] = (float)z;
    }
}

// ---------------- launch ----------------
extern "C" void kernel_launch(void* const* d_in, const int* in_sizes, int n_in,
                              void* d_out, int out_size) {
    const int* x = nullptr;
    const float* emit = nullptr;
    const float* trans = nullptr;
    for (int i = 0; i < n_in; i++) {
        if (in_sizes[i] == 8192)         x     = (const int*)d_in[i];
        else if (in_sizes[i] == NT * NT) trans = (const float*)d_in[i];
        else                             emit  = (const float*)d_in[i];
    }
    float* out = (float*)d_out;

    const int FOLD_SMEM = NT * RAWPITCH * 4 + 8192 * 4;   // 67584 + 32768 = 100352
    const int COMB_SMEM = 2 * NT * NT * 4;                // 131072
    cudaFuncSetAttribute(fold4_kernel,  cudaFuncAttributeMaxDynamicSharedMemorySize, FOLD_SMEM);
    cudaFuncSetAttribute(combine_kernel, cudaFuncAttributeMaxDynamicSharedMemorySize, COMB_SMEM);

    prep_E<<<1, NT>>>(trans);
    prep_D<<<TSTEPS, NT>>>(x, emit);
    chunk_kernel<<<NCH, 128>>>();
    fold4_kernel<<<NQ, 128, FOLD_SMEM>>>();
    combine_kernel<<<1, 512, COMB_SMEM>>>(trans, out);
}